// round 1
// baseline (speedup 1.0000x reference)
#include <cuda_runtime.h>
#include <cstdint>

// AttentionDownsampler: fused single-read implementation.
//   hr_feats (8,384,112,112) fp32 -> out (8,384,16,16) fp32
// Patches are non-overlapping 7x7 tiles (stride == K == 7).
// One CTA per (b, ph, pw) patch: stage 49x384 floats in smem, compute
// logits, masked softmax over 49 positions, then per-channel weighted sum.

#define DIM     384
#define KS      7
#define NP      49            // KS*KS
#define PAD     385           // DIM+1, breaks 384%32==0 bank pattern
#define HW      112
#define FINALN  16
#define THREADS 384
#define DROP_P  0.2f

// dynamic smem: tile[NP*PAD] + awsh[DIM] + lsh[NP] + attn[NP]
#define SMEM_FLOATS (NP * PAD + DIM + NP + NP)
#define SMEM_BYTES  (SMEM_FLOATS * 4)

__global__ void __launch_bounds__(THREADS, 2)
attn_downsampler_kernel(const float* __restrict__ hr,
                        const float* __restrict__ du,
                        const float* __restrict__ aw,
                        const float* __restrict__ ab,
                        const float* __restrict__ wmat,
                        const float* __restrict__ bmat,
                        float* __restrict__ out)
{
    extern __shared__ float smem[];
    float* tile = smem;                  // [NP][PAD], layout tile[p*PAD + c]
    float* awsh = tile + NP * PAD;       // [DIM]
    float* lsh  = awsh + DIM;            // [NP] raw dot-products
    float* attn = lsh + NP;              // [NP] softmax weights

    const int bid = blockIdx.x;
    const int pw  = bid & 15;
    const int ph  = (bid >> 4) & 15;
    const int pb  = bid >> 8;

    const int tid  = threadIdx.x;
    const int lane = tid & 31;
    const int wid  = tid >> 5;

    // base of this patch for channel 0
    const float* base = hr + (size_t)pb * DIM * (HW * HW)
                           + (size_t)(ph * KS) * HW + pw * KS;

    awsh[tid] = aw[tid];

    // ---- stage patch: 49*384 = 18816 elements, 49 iters/thread ----
    // i enumerates (c, dy, dx) with dx fastest -> consecutive lanes hit
    // consecutive x (7-float runs), maximizing sector use.
    #pragma unroll 7
    for (int k = 0; k < NP; k++) {
        int i  = k * THREADS + tid;      // 0 .. 18815
        int c  = i / NP;
        int p  = i - c * NP;             // dy*7 + dx
        int dy = p / KS;
        int dx = p - dy * KS;
        float v = __ldg(base + (size_t)c * (HW * HW) + dy * HW + dx);
        tile[p * PAD + c] = v;
    }
    __syncthreads();

    // ---- logits: 49 dot products of length 384, warp per p ----
    for (int p = wid; p < NP; p += THREADS / 32) {
        const float* tp = tile + p * PAD;
        float s = 0.f;
        #pragma unroll
        for (int c = lane; c < DIM; c += 32)
            s = fmaf(tp[c], awsh[c], s);
        #pragma unroll
        for (int o = 16; o; o >>= 1)
            s += __shfl_xor_sync(0xffffffffu, s, o);
        if (lane == 0) lsh[p] = s;
    }
    __syncthreads();

    // ---- masked affine + softmax over 49 (warp 0) ----
    if (wid == 0) {
        const float m   = (du[(pb * FINALN + ph) * FINALN + pw] > DROP_P) ? 1.f : 0.f;
        const float abv = ab[0];
        const int p1 = lane + 32;
        float v0 = -1e30f, v1 = -1e30f;
        if (lane < NP) v0 = (lsh[lane] + abv) * m * wmat[lane] + bmat[lane];
        if (p1   < NP) v1 = (lsh[p1]   + abv) * m * wmat[p1]   + bmat[p1];
        float mx = fmaxf(v0, v1);
        #pragma unroll
        for (int o = 16; o; o >>= 1)
            mx = fmaxf(mx, __shfl_xor_sync(0xffffffffu, mx, o));
        float e0 = (lane < NP) ? __expf(v0 - mx) : 0.f;
        float e1 = (p1   < NP) ? __expf(v1 - mx) : 0.f;
        float s = e0 + e1;
        #pragma unroll
        for (int o = 16; o; o >>= 1)
            s += __shfl_xor_sync(0xffffffffu, s, o);
        const float inv = 1.f / s;
        if (lane < NP) attn[lane] = e0 * inv;
        if (p1   < NP) attn[p1]   = e1 * inv;
    }
    __syncthreads();

    // ---- output: one channel per thread, sum over 49 positions ----
    float acc = 0.f;
    #pragma unroll
    for (int p = 0; p < NP; p++)
        acc = fmaf(tile[p * PAD + tid], attn[p], acc);

    out[((size_t)(pb * DIM + tid) * FINALN + ph) * FINALN + pw] = acc;
}

extern "C" void kernel_launch(void* const* d_in, const int* in_sizes, int n_in,
                              void* d_out, int out_size)
{
    const float* hr   = (const float*)d_in[0];   // (8,384,112,112)
    // d_in[1] = guidance (unused)
    const float* du   = (const float*)d_in[2];   // (8,16,16,1)
    const float* aw   = (const float*)d_in[3];   // (384,)
    const float* ab   = (const float*)d_in[4];   // (1,)
    const float* wmat = (const float*)d_in[5];   // (7,7)
    const float* bmat = (const float*)d_in[6];   // (7,7)
    float* out = (float*)d_out;                  // (8,384,16,16)

    cudaFuncSetAttribute(attn_downsampler_kernel,
                         cudaFuncAttributeMaxDynamicSharedMemorySize, SMEM_BYTES);

    dim3 grid(8 * FINALN * FINALN);              // 2048 patches
    attn_downsampler_kernel<<<grid, THREADS, SMEM_BYTES>>>(
        hr, du, aw, ab, wmat, bmat, out);
}